// round 13
// baseline (speedup 1.0000x reference)
#include <cuda_runtime.h>
#include <cstdint>

#define IN_DIM 128
#define W_DIM 160
#define OUT_DIM 224
#define NN_PAD 53248          // 1024 threads * 52 nodes, int4-aligned
#define MAX_EDGES 800000
#define EPT 16                // sorted edges per 8-thread group

__device__ int g_count[NN_PAD];
__device__ int g_start[NN_PAD];
__device__ int g_cursor[NN_PAD];
__device__ int g_perm[MAX_EDGES];

// NOTE: no "memory" clobber — RED targets 'out', which is never read in this
// kernel, and removing the clobber lets ptxas batch subsequent loads above
// flushes (the flush was acting as a scheduling barrier in the hot loop).
__device__ __forceinline__ void red_add_v4(float* addr, float a, float b, float c, float d) {
    asm volatile("red.global.add.v4.f32 [%0], {%1, %2, %3, %4};"
                 :: "l"(addr), "f"(a), "f"(b), "f"(c), "f"(d));
}

// ---------- preprocessing ----------

// Fused: zero output + zero histogram counters (incl. scan padding).
__global__ void zero_all_kernel(float4* __restrict__ out, int n4) {
    int i = blockIdx.x * blockDim.x + threadIdx.x;
    if (i < n4) out[i] = make_float4(0.f, 0.f, 0.f, 0.f);
    if (i < NN_PAD) g_count[i] = 0;
}

// 2 edges per thread via int4.
__global__ void hist_kernel(const int4* __restrict__ eidx2, int n_pairs, int n_edges) {
    int i = blockIdx.x * blockDim.x + threadIdx.x;
    if (i < n_pairs) {
        int4 e2 = __ldcs(&eidx2[i]);
        atomicAdd(&g_count[e2.y], 1);
        if (2 * i + 1 < n_edges) atomicAdd(&g_count[e2.w], 1);
    }
}

// Single-kernel exclusive scan over NN_PAD counts: 1024 threads, 52 nodes each.
// All loads independent (13 int4 per thread, fully unrolled) -> MLP-covered.
__global__ __launch_bounds__(1024) void scan_fused_kernel() {
    __shared__ int warpsum[32];
    int t = threadIdx.x;
    int lane = t & 31, wid = t >> 5;

    int4 c[13];
    const int4* cp = (const int4*)g_count + t * 13;
    #pragma unroll
    for (int j = 0; j < 13; j++) c[j] = cp[j];

    int s = 0;
    #pragma unroll
    for (int j = 0; j < 13; j++) s += c[j].x + c[j].y + c[j].z + c[j].w;

    // inclusive warp scan of thread sums
    int v = s;
    #pragma unroll
    for (int off = 1; off < 32; off <<= 1) {
        int u = __shfl_up_sync(0xffffffffu, v, off);
        if (lane >= off) v += u;
    }
    if (lane == 31) warpsum[wid] = v;
    __syncthreads();
    if (wid == 0) {
        int w = warpsum[lane];
        #pragma unroll
        for (int off = 1; off < 32; off <<= 1) {
            int u = __shfl_up_sync(0xffffffffu, w, off);
            if (lane >= off) w += u;
        }
        warpsum[lane] = w;
    }
    __syncthreads();

    int run = ((wid > 0) ? warpsum[wid - 1] : 0) + (v - s);  // exclusive prefix

    int* sp = g_start + t * 52;
    int* qp = g_cursor + t * 52;
    #pragma unroll
    for (int j = 0; j < 13; j++) {
        sp[4*j+0] = run; qp[4*j+0] = run; run += c[j].x;
        sp[4*j+1] = run; qp[4*j+1] = run; run += c[j].y;
        sp[4*j+2] = run; qp[4*j+2] = run; run += c[j].z;
        sp[4*j+3] = run; qp[4*j+3] = run; run += c[j].w;
    }
}

// 2 edges per thread via int4.
__global__ void scatter_kernel(const int4* __restrict__ eidx2, int n_pairs, int n_edges) {
    int i = blockIdx.x * blockDim.x + threadIdx.x;
    if (i < n_pairs) {
        int4 e2 = __ldcs(&eidx2[i]);
        int pos0 = atomicAdd(&g_cursor[e2.y], 1);
        g_perm[pos0] = 2 * i;
        if (2 * i + 1 < n_edges) {
            int pos1 = atomicAdd(&g_cursor[e2.w], 1);
            g_perm[pos1] = 2 * i + 1;
        }
    }
}

// ---------- main: edge-chunked over dst-sorted order, register combining ----------

__device__ __forceinline__ void flush_acc(float* __restrict__ out, int dst, int g,
                                          const float4* acc) {
    float* ob = out + (size_t)dst * OUT_DIM + 4 * g;
    #pragma unroll
    for (int s = 0; s < 7; s++)
        red_add_v4(ob + 32 * s, acc[s].x, acc[s].y, acc[s].z, acc[s].w);
}

__global__ __launch_bounds__(256) void conv_main_kernel(
    const float* __restrict__ nf,        // [n_nodes, 128]
    const float4* __restrict__ ang,      // [n_edges, 4]
    const int2* __restrict__ eidx,       // [n_edges, 2]
    const float* __restrict__ tp,        // [n_edges, 160]
    float* __restrict__ out,             // [n_nodes, 224]
    int n_edges)
{
    const float INV_SQRT3 = 0.5773502691896258f;
    const float INV_SQRT2 = 0.7071067811865476f;

    int tid = blockIdx.x * 256 + threadIdx.x;
    int group = tid >> 3;
    int g = tid & 7;
    int base = group * EPT;
    if (base >= n_edges) return;

    float4 acc[7];
    #pragma unroll
    for (int s = 0; s < 7; s++) acc[s] = make_float4(0.f, 0.f, 0.f, 0.f);
    int cur_dst = -1;

    int p_next = __ldg(&g_perm[base]);
    int2 se_next = __ldg(&eidx[p_next]);

    #pragma unroll 4
    for (int k = 0; k < EPT; k++) {
        int i = base + k;
        if (i >= n_edges) break;
        int p = p_next;
        int2 se = se_next;
        if (i + 1 < n_edges && k + 1 < EPT) {
            p_next = __ldg(&g_perm[i + 1]);
            se_next = __ldg(&eidx[p_next]);
        }

        if (se.y != cur_dst) {
            if (cur_dst >= 0) {
                flush_acc(out, cur_dst, g, acc);
                #pragma unroll
                for (int s = 0; s < 7; s++) acc[s] = make_float4(0.f, 0.f, 0.f, 0.f);
            }
            cur_dst = se.y;
        }

        float4 y = __ldcs(&ang[p]);
        float y0 = y.x, yx = y.y, yy = y.z, yz = y.w;

        const float4* hb = (const float4*)(nf + (size_t)se.x * IN_DIM);
        float4 h0v  = __ldg(&hb[g]);
        float4 h1xv = __ldg(&hb[8 + g]);
        float4 h1yv = __ldg(&hb[16 + g]);
        float4 h1zv = __ldg(&hb[24 + g]);

        const float4* wb = (const float4*)(tp + (size_t)p * W_DIM);
        float4 w0v = __ldcs(&wb[g]);
        float4 w1v = __ldcs(&wb[8 + g]);
        float4 w2v = __ldcs(&wb[16 + g]);
        float4 w3v = __ldcs(&wb[24 + g]);
        float4 w4v = __ldcs(&wb[32 + g]);

        const float* h0p  = (const float*)&h0v;
        const float* h1xp = (const float*)&h1xv;
        const float* h1yp = (const float*)&h1yv;
        const float* h1zp = (const float*)&h1zv;
        const float* w0p  = (const float*)&w0v;
        const float* w1p  = (const float*)&w1v;
        const float* w2p  = (const float*)&w2v;
        const float* w3p  = (const float*)&w3v;
        const float* w4p  = (const float*)&w4v;
        float* a0 = (float*)&acc[0];
        float* a1 = (float*)&acc[1];
        float* a2 = (float*)&acc[2];
        float* a3 = (float*)&acc[3];
        float* a4 = (float*)&acc[4];
        float* a5 = (float*)&acc[5];
        float* a6 = (float*)&acc[6];

        #pragma unroll
        for (int c = 0; c < 4; c++) {
            float H0 = h0p[c], Hx = h1xp[c], Hy = h1yp[c], Hz = h1zp[c];
            float W0 = w0p[c], W1 = w1p[c], W2 = w2p[c], W3 = w3p[c], W4 = w4p[c];

            float dot = Hx * yx + Hy * yy + Hz * yz;
            a0[c] += W0 * (H0 * y0) + (W3 * INV_SQRT3) * dot;

            float a = W1 * H0;
            float b = W2 * y0;
            a1[c] += a * yx + b * Hx;
            a2[c] += a * yy + b * Hy;
            a3[c] += a * yz + b * Hz;

            float s = W4 * INV_SQRT2;
            a4[c] += s * (Hy * yz - Hz * yy);
            a5[c] += s * (Hz * yx - Hx * yz);
            a6[c] += s * (Hx * yy - Hy * yx);
        }
    }

    if (cur_dst >= 0) flush_acc(out, cur_dst, g, acc);
}

extern "C" void kernel_launch(void* const* d_in, const int* in_sizes, int n_in,
                              void* d_out, int out_size) {
    const float*  nf   = (const float*)d_in[0];      // node_features [n,128]
    const float4* ang  = (const float4*)d_in[1];     // edge_angular  [E,4]
    const int2*   eidx = (const int2*)d_in[2];       // edge_index    [E,2] int32
    const float*  tp   = (const float*)d_in[3];      // tp_weights    [E,160]
    float*        out  = (float*)d_out;

    int n_edges = in_sizes[1] / 4;
    int n4 = out_size / 4;
    int n_pairs = (n_edges + 1) / 2;

    int zmax = (n4 > NN_PAD) ? n4 : NN_PAD;
    zero_all_kernel<<<(zmax + 255) / 256, 256>>>((float4*)d_out, n4);
    hist_kernel<<<(n_pairs + 255) / 256, 256>>>((const int4*)eidx, n_pairs, n_edges);
    scan_fused_kernel<<<1, 1024>>>();
    scatter_kernel<<<(n_pairs + 255) / 256, 256>>>((const int4*)eidx, n_pairs, n_edges);

    int groups = (n_edges + EPT - 1) / EPT;
    int total_threads = groups * 8;
    int blocks = (total_threads + 255) / 256;
    conv_main_kernel<<<blocks, 256>>>(nf, ang, eidx, tp, out, n_edges);
}

// round 14
// speedup vs baseline: 1.0323x; 1.0323x over previous
#include <cuda_runtime.h>
#include <cstdint>

#define IN_DIM 128
#define W_DIM 160
#define OUT_DIM 224
#define NN_PAD 53248          // 1024 threads * 52 nodes, int4-aligned
#define MAX_EDGES 800064      // + pad so prefetch needs no guard
#define EPT 32                // sorted edges per 8-thread group (800000/32 exact)

__device__ int g_count[NN_PAD];
__device__ int g_start[NN_PAD];
__device__ int g_cursor[NN_PAD];
__device__ int g_perm[MAX_EDGES];

__device__ __forceinline__ void red_add_v4(float* addr, float a, float b, float c, float d) {
    asm volatile("red.global.add.v4.f32 [%0], {%1, %2, %3, %4};"
                 :: "l"(addr), "f"(a), "f"(b), "f"(c), "f"(d)
                 : "memory");
}

// ---------- preprocessing ----------

// Fused: zero output + zero histogram counters + perm padding.
__global__ void zero_all_kernel(float4* __restrict__ out, int n4, int n_edges) {
    int i = blockIdx.x * blockDim.x + threadIdx.x;
    if (i < n4) out[i] = make_float4(0.f, 0.f, 0.f, 0.f);
    if (i < NN_PAD) g_count[i] = 0;
    if (i < 64 && n_edges + i < MAX_EDGES) g_perm[n_edges + i] = 0;
}

__global__ void hist_kernel(const int2* __restrict__ eidx, int n_edges) {
    int i = blockIdx.x * blockDim.x + threadIdx.x;
    if (i < n_edges) atomicAdd(&g_count[__ldg(&eidx[i]).y], 1);
}

// Single-kernel exclusive scan over NN_PAD counts: 1024 threads, 52 nodes each.
// All loads independent (13 int4 per thread, fully unrolled) -> MLP-covered.
__global__ __launch_bounds__(1024) void scan_fused_kernel() {
    __shared__ int warpsum[32];
    int t = threadIdx.x;
    int lane = t & 31, wid = t >> 5;

    int4 c[13];
    const int4* cp = (const int4*)g_count + t * 13;
    #pragma unroll
    for (int j = 0; j < 13; j++) c[j] = cp[j];

    int s = 0;
    #pragma unroll
    for (int j = 0; j < 13; j++) s += c[j].x + c[j].y + c[j].z + c[j].w;

    // inclusive warp scan of thread sums
    int v = s;
    #pragma unroll
    for (int off = 1; off < 32; off <<= 1) {
        int u = __shfl_up_sync(0xffffffffu, v, off);
        if (lane >= off) v += u;
    }
    if (lane == 31) warpsum[wid] = v;
    __syncthreads();
    if (wid == 0) {
        int w = warpsum[lane];
        #pragma unroll
        for (int off = 1; off < 32; off <<= 1) {
            int u = __shfl_up_sync(0xffffffffu, w, off);
            if (lane >= off) w += u;
        }
        warpsum[lane] = w;
    }
    __syncthreads();

    int run = ((wid > 0) ? warpsum[wid - 1] : 0) + (v - s);  // exclusive prefix

    int* sp = g_start + t * 52;
    int* qp = g_cursor + t * 52;
    #pragma unroll
    for (int j = 0; j < 13; j++) {
        sp[4*j+0] = run; qp[4*j+0] = run; run += c[j].x;
        sp[4*j+1] = run; qp[4*j+1] = run; run += c[j].y;
        sp[4*j+2] = run; qp[4*j+2] = run; run += c[j].z;
        sp[4*j+3] = run; qp[4*j+3] = run; run += c[j].w;
    }
}

__global__ void scatter_kernel(const int2* __restrict__ eidx, int n_edges) {
    int i = blockIdx.x * blockDim.x + threadIdx.x;
    if (i < n_edges) {
        int dst = __ldg(&eidx[i]).y;
        int pos = atomicAdd(&g_cursor[dst], 1);
        g_perm[pos] = i;
    }
}

// ---------- main: edge-chunked over dst-sorted order, register combining ----------

__device__ __forceinline__ void flush_acc(float* __restrict__ out, int dst, int g,
                                          const float4* acc) {
    float* ob = out + (size_t)dst * OUT_DIM + 4 * g;
    #pragma unroll
    for (int s = 0; s < 7; s++)
        red_add_v4(ob + 32 * s, acc[s].x, acc[s].y, acc[s].z, acc[s].w);
}

__global__ __launch_bounds__(256) void conv_main_kernel(
    const float* __restrict__ nf,        // [n_nodes, 128]
    const float4* __restrict__ ang,      // [n_edges, 4]
    const int2* __restrict__ eidx,       // [n_edges, 2]
    const float* __restrict__ tp,        // [n_edges, 160]
    float* __restrict__ out,             // [n_nodes, 224]
    int n_edges)
{
    const float INV_SQRT3 = 0.5773502691896258f;
    const float INV_SQRT2 = 0.7071067811865476f;

    int tid = blockIdx.x * 256 + threadIdx.x;
    int group = tid >> 3;
    int g = tid & 7;
    int base = group * EPT;
    if (base >= n_edges) return;

    float4 acc[7];
    #pragma unroll
    for (int s = 0; s < 7; s++) acc[s] = make_float4(0.f, 0.f, 0.f, 0.f);
    int cur_dst = -1;

    int p_next = __ldg(&g_perm[base]);
    int2 se_next = __ldg(&eidx[p_next]);

    // Chunks are exact (n_edges % EPT == 0) and g_perm is padded:
    // no bounds check, no prefetch guard — uniform unrollable body.
    #pragma unroll 4
    for (int k = 0; k < EPT; k++) {
        int i = base + k;
        int p = p_next;
        int2 se = se_next;
        p_next = __ldg(&g_perm[i + 1]);
        se_next = __ldg(&eidx[p_next]);

        if (se.y != cur_dst) {
            if (cur_dst >= 0) {
                flush_acc(out, cur_dst, g, acc);
                #pragma unroll
                for (int s = 0; s < 7; s++) acc[s] = make_float4(0.f, 0.f, 0.f, 0.f);
            }
            cur_dst = se.y;
        }

        float4 y = __ldcs(&ang[p]);
        float y0 = y.x, yx = y.y, yy = y.z, yz = y.w;

        const float4* hb = (const float4*)(nf + (size_t)se.x * IN_DIM);
        float4 h0v  = __ldg(&hb[g]);
        float4 h1xv = __ldg(&hb[8 + g]);
        float4 h1yv = __ldg(&hb[16 + g]);
        float4 h1zv = __ldg(&hb[24 + g]);

        const float4* wb = (const float4*)(tp + (size_t)p * W_DIM);
        float4 w0v = __ldcs(&wb[g]);
        float4 w1v = __ldcs(&wb[8 + g]);
        float4 w2v = __ldcs(&wb[16 + g]);
        float4 w3v = __ldcs(&wb[24 + g]);
        float4 w4v = __ldcs(&wb[32 + g]);

        const float* h0p  = (const float*)&h0v;
        const float* h1xp = (const float*)&h1xv;
        const float* h1yp = (const float*)&h1yv;
        const float* h1zp = (const float*)&h1zv;
        const float* w0p  = (const float*)&w0v;
        const float* w1p  = (const float*)&w1v;
        const float* w2p  = (const float*)&w2v;
        const float* w3p  = (const float*)&w3v;
        const float* w4p  = (const float*)&w4v;
        float* a0 = (float*)&acc[0];
        float* a1 = (float*)&acc[1];
        float* a2 = (float*)&acc[2];
        float* a3 = (float*)&acc[3];
        float* a4 = (float*)&acc[4];
        float* a5 = (float*)&acc[5];
        float* a6 = (float*)&acc[6];

        #pragma unroll
        for (int c = 0; c < 4; c++) {
            float H0 = h0p[c], Hx = h1xp[c], Hy = h1yp[c], Hz = h1zp[c];
            float W0 = w0p[c], W1 = w1p[c], W2 = w2p[c], W3 = w3p[c], W4 = w4p[c];

            float dot = Hx * yx + Hy * yy + Hz * yz;
            a0[c] += W0 * (H0 * y0) + (W3 * INV_SQRT3) * dot;

            float a = W1 * H0;
            float b = W2 * y0;
            a1[c] += a * yx + b * Hx;
            a2[c] += a * yy + b * Hy;
            a3[c] += a * yz + b * Hz;

            float s = W4 * INV_SQRT2;
            a4[c] += s * (Hy * yz - Hz * yy);
            a5[c] += s * (Hz * yx - Hx * yz);
            a6[c] += s * (Hx * yy - Hy * yx);
        }
    }

    if (cur_dst >= 0) flush_acc(out, cur_dst, g, acc);
}

extern "C" void kernel_launch(void* const* d_in, const int* in_sizes, int n_in,
                              void* d_out, int out_size) {
    const float*  nf   = (const float*)d_in[0];      // node_features [n,128]
    const float4* ang  = (const float4*)d_in[1];     // edge_angular  [E,4]
    const int2*   eidx = (const int2*)d_in[2];       // edge_index    [E,2] int32
    const float*  tp   = (const float*)d_in[3];      // tp_weights    [E,160]
    float*        out  = (float*)d_out;

    int n_edges = in_sizes[1] / 4;
    int n4 = out_size / 4;

    int zmax = (n4 > NN_PAD) ? n4 : NN_PAD;
    zero_all_kernel<<<(zmax + 255) / 256, 256>>>((float4*)d_out, n4, n_edges);
    hist_kernel<<<(n_edges + 255) / 256, 256>>>(eidx, n_edges);
    scan_fused_kernel<<<1, 1024>>>();
    scatter_kernel<<<(n_edges + 255) / 256, 256>>>(eidx, n_edges);

    int groups = (n_edges + EPT - 1) / EPT;
    int total_threads = groups * 8;
    int blocks = (total_threads + 255) / 256;
    conv_main_kernel<<<blocks, 256>>>(nf, ang, eidx, tp, out, n_edges);
}